// round 3
// baseline (speedup 1.0000x reference)
#include <cuda_runtime.h>
#include <cuda_fp16.h>
#include <cstdint>

// FastRotation: per-filter Rodrigues rotation of the canonical 5x5x5 grid +
// trilinear resample with zero padding.
//
// R3: volume stored in smem as half2 x-pairs P[z][y][x] = (v[x], v[x+1]) over
// a zero-padded 9x9x9 grid. The 8-tap trilinear gather becomes 4x LDS.32
// (half the smem bytes, half the random bank draws vs fp32 scalar taps).
// Interpolation math stays fp32. One warp per filter, 4 points per lane.

#define WARPS_PER_BLOCK 8
#define TPB (WARPS_PER_BLOCK * 32)
#define PADV 736   // 9*9*9 = 729 half2, padded to multiple of 4 words

__global__ __launch_bounds__(TPB)
void fastrot_kernel(const float* __restrict__ filt,
                    const float* __restrict__ theta_v,
                    const float* __restrict__ theta,
                    float* __restrict__ out,
                    int n)
{
    __shared__ __align__(16) __half2 svol[WARPS_PER_BLOCK][PADV];

    const int lane = threadIdx.x & 31;
    const int wb   = threadIdx.x >> 5;
    const int fidx = blockIdx.x * WARPS_PER_BLOCK + wb;
    if (fidx >= n) return;

    __half2* sp = svol[wb];

    // ---- zero-fill padded pair-volume (736 * 4B = 184 float4) ----
    {
        float4* sp4 = (float4*)sp;
        const float4 z4 = make_float4(0.f, 0.f, 0.f, 0.f);
        #pragma unroll
        for (int k = 0; k < 6; k++) {
            const int idx = lane + k * 32;
            if (idx < PADV / 4) sp4[idx] = z4;
        }
    }
    __syncwarp();

    // ---- build x-pair entries directly from global (150 nonzero entries) ----
    // Entry e -> (i, j, xp) with i,j in [0..4], xp in [0..5]; padded x = xp+1.
    // P[(i+2)*81 + (j+2)*9 + (xp+1)] = ( v(l=xp-1), v(l=xp) ), OOB -> 0.
    const float* f = filt + (size_t)fidx * 125;
    #pragma unroll
    for (int k = 0; k < 5; k++) {
        const int e = lane + k * 32;
        if (e < 150) {
            const int i  = e / 30;
            const int r  = e - i * 30;
            const int j  = r / 6;
            const int xp = r - j * 6;
            const int l0 = xp - 1;                 // [-1..4]
            const float* fb = f + i * 25 + j * 5;
            const float e0 = (l0 >= 0) ? fb[l0]     : 0.0f;
            const float e1 = (l0 <  4) ? fb[l0 + 1] : 0.0f;
            sp[(i + 2) * 81 + (j + 2) * 9 + (xp + 1)] = __floats2half2_rn(e0, e1);
        }
    }

    // ---- Rodrigues matrix, pre-doubled (pixel = 2*g + 2) ----
    const float tvx = theta_v[3 * fidx + 0];
    const float tvy = theta_v[3 * fidx + 1];
    const float tvz = theta_v[3 * fidx + 2];
    const float th  = theta[fidx];

    const float inv = rsqrtf(fmaxf(tvx * tvx + tvy * tvy + tvz * tvz, 1e-24f));
    const float vx = tvx * inv, vy = tvy * inv, vz = tvz * inv;

    float s, ct;
    __sincosf(th, &s, &ct);
    const float c = 1.0f - ct;

    const float a00 = 2.0f * (1.0f + c * (-vz * vz - vy * vy));
    const float a01 = 2.0f * (-s * vz + c * (vx * vy));
    const float a02 = 2.0f * ( s * vy + c * (vx * vz));
    const float a10 = 2.0f * ( s * vz + c * (vx * vy));
    const float a11 = 2.0f * (1.0f + c * (-vz * vz - vx * vx));
    const float a12 = 2.0f * (-s * vx + c * (vy * vz));
    const float a20 = 2.0f * (-s * vy + c * (vx * vz));
    const float a21 = 2.0f * ( s * vx + c * (vy * vz));
    const float a22 = 2.0f * (1.0f + c * (-vy * vy - vx * vx));

    __syncwarp();

    float* o = out + (size_t)fidx * 125;

    #pragma unroll
    for (int rep = 0; rep < 4; rep++) {
        const int p = lane + rep * 32;
        if (p >= 125) break;

        // p = i*25 + j*5 + l ; base coords c[k] = -1 + 0.5*k
        const int i = p / 25;
        const int r = p - i * 25;
        const int j = r / 5;
        const int l = r - j * 5;
        const float px = -1.0f + 0.5f * (float)i;
        const float py = -1.0f + 0.5f * (float)j;
        const float pz = -1.0f + 0.5f * (float)l;

        const float x = fmaf(px, a00, fmaf(py, a10, fmaf(pz, a20, 2.0f)));
        const float y = fmaf(px, a01, fmaf(py, a11, fmaf(pz, a21, 2.0f)));
        const float z = fmaf(px, a02, fmaf(py, a12, fmaf(pz, a22, 2.0f)));

        const float xf = floorf(x), yf = floorf(y), zf = floorf(z);
        const float wx = x - xf,   wy = y - yf,   wz = z - zf;
        const int x0 = (int)xf, y0 = (int)yf, z0 = (int)zf;

        // padded pair index: (z0+2)*81 + (y0+2)*9 + (x0+2); entry holds taps (x0, x0+1)
        const __half2* q = sp + (z0 * 81 + y0 * 9 + x0 + 182);

        const float2 t00 = __half22float2(q[ 0]);
        const float2 t01 = __half22float2(q[ 9]);
        const float2 t10 = __half22float2(q[81]);
        const float2 t11 = __half22float2(q[90]);

        const float cx = 1.0f - wx, cy = 1.0f - wy, cz = 1.0f - wz;
        const float c00 = cz * cy, c01 = cz * wy, c10 = wz * cy, c11 = wz * wy;

        const float s00 = fmaf(t00.y, wx, t00.x * cx);
        const float s01 = fmaf(t01.y, wx, t01.x * cx);
        const float s10 = fmaf(t10.y, wx, t10.x * cx);
        const float s11 = fmaf(t11.y, wx, t11.x * cx);

        o[p] = fmaf(c11, s11, fmaf(c10, s10, fmaf(c01, s01, c00 * s00)));
    }
}

extern "C" void kernel_launch(void* const* d_in, const int* in_sizes, int n_in,
                              void* d_out, int out_size)
{
    const float* filt    = (const float*)d_in[0];
    const float* theta_v = (const float*)d_in[1];
    const float* theta   = (const float*)d_in[2];
    float* out           = (float*)d_out;

    const int n = in_sizes[2];  // one theta per filter

    const int blocks = (n + WARPS_PER_BLOCK - 1) / WARPS_PER_BLOCK;
    fastrot_kernel<<<blocks, TPB>>>(filt, theta_v, theta, out, n);
}